// round 15
// baseline (speedup 1.0000x reference)
#include <cuda_runtime.h>
#include <cstdint>
#include <math.h>

#define BATCH 32
#define TLEN  1024
#define IDIM  512
#define HDIM  1024
#define G4    4096
#define KP    512          // k-pairs in recurrence (HDIM/2)
#define KPCH  64           // k-pairs per staged chunk
#define NCH   8
#define CHBYTES (KPCH * 64 * 4)   // 16384 bytes per chunk
#define GRID  128
#define NTH   512
#define GSTR  33

// ---------------- static device scratch (allocation-free) ------------------
__device__ float g_Xg[(size_t)BATCH * TLEN * G4];   // [t*32+b][4096], includes biases
__device__ float g_h[2][HDIM * BATCH];              // [kp][b] float2: idx kp*64 + b*2 + par
__device__ volatile unsigned g_bar;
__device__ unsigned g_done;

// ---------------- helpers ---------------------------------------------------
__device__ __forceinline__ void ffma2(unsigned long long& d,
                                      unsigned long long a,
                                      unsigned long long b) {
    asm("fma.rn.f32x2 %0, %1, %2, %0;" : "+l"(d) : "l"(a), "l"(b));
}
__device__ __forceinline__ float acc_sum(unsigned long long v) {
    return __uint_as_float((unsigned)v) + __uint_as_float((unsigned)(v >> 32));
}
__device__ __forceinline__ float sigm(float x) { return 1.f / (1.f + __expf(-x)); }
__device__ __forceinline__ float tanh_f(float x) { return 1.f - 2.f / (__expf(2.f * x) + 1.f); }

__device__ __forceinline__ void mbar_init(unsigned mbar, unsigned cnt) {
    asm volatile("mbarrier.init.shared.b64 [%0], %1;" :: "r"(mbar), "r"(cnt) : "memory");
}
__device__ __forceinline__ void mbar_expect_tx(unsigned mbar, unsigned bytes) {
    asm volatile("mbarrier.arrive.expect_tx.shared.b64 _, [%0], %1;"
                 :: "r"(mbar), "r"(bytes) : "memory");
}
__device__ __forceinline__ void bulk_g2s(unsigned sdst, const void* gsrc,
                                         unsigned bytes, unsigned mbar) {
    asm volatile(
        "cp.async.bulk.shared::cta.global.mbarrier::complete_tx::bytes [%0], [%1], %2, [%3];"
        :: "r"(sdst), "l"(gsrc), "r"(bytes), "r"(mbar) : "memory");
}
__device__ __forceinline__ void mbar_wait(unsigned mbar, unsigned parity) {
    unsigned done;
    asm volatile(
        "{\n\t.reg .pred p;\n\t"
        "mbarrier.try_wait.parity.acquire.cta.shared::cta.b64 p, [%1], %2;\n\t"
        "selp.b32 %0, 1, 0, p;\n\t}"
        : "=r"(done) : "r"(mbar), "r"(parity) : "memory");
    if (!done) {
        asm volatile(
            "{\n\t.reg .pred P1;\n\t"
            "WL_%=:\n\t"
            "mbarrier.try_wait.parity.acquire.cta.shared::cta.b64 P1, [%0], %1, 0x989680;\n\t"
            "@P1 bra.uni WD_%=;\n\t"
            "bra.uni WL_%=;\n\t"
            "WD_%=:\n\t}"
            :: "r"(mbar), "r"(parity) : "memory");
    }
}

// ======================= Kernel 1: Xg = X @ W_ih^T + (b_ih + b_hh) =========
#define BM 128
#define BN 64
#define BK 16
#define SAS 18
#define SBS 18

__global__ __launch_bounds__(256) void xg_gemm(const float* __restrict__ X,
                                               const float* __restrict__ Wih,
                                               const float* __restrict__ bih,
                                               const float* __restrict__ bhh) {
    __shared__ float sA[BM * SAS];
    __shared__ float sB[BN * SBS];

    const int tid = threadIdx.x;
    const int tx = tid & 15;
    const int ty = tid >> 4;
    const int n0 = blockIdx.y * BM;
    const int c0 = blockIdx.x * BN;

    unsigned long long acc2[8][4];
#pragma unroll
    for (int i = 0; i < 8; ++i)
#pragma unroll
        for (int j = 0; j < 4; ++j) acc2[i][j] = 0ull;

    for (int k0 = 0; k0 < IDIM; k0 += BK) {
        {
            const int m = tid >> 1;
            const int kk = (tid & 1) * 8;
            const float* src = X + (size_t)(n0 + m) * IDIM + k0 + kk;
            float4 v0 = *(const float4*)(src);
            float4 v1 = *(const float4*)(src + 4);
            float* d = sA + m * SAS + kk;
            d[0] = v0.x; d[1] = v0.y; d[2] = v0.z; d[3] = v0.w;
            d[4] = v1.x; d[5] = v1.y; d[6] = v1.z; d[7] = v1.w;
        }
        {
            const int m = tid >> 2;
            const int kk = (tid & 3) * 4;
            float4 v = *(const float4*)(Wih + (size_t)(c0 + m) * IDIM + k0 + kk);
            float* d = sB + m * SBS + kk;
            d[0] = v.x; d[1] = v.y; d[2] = v.z; d[3] = v.w;
        }
        __syncthreads();

#pragma unroll
        for (int kp = 0; kp < BK / 2; ++kp) {
            unsigned long long a2[8], b2[4];
#pragma unroll
            for (int i = 0; i < 8; ++i)
                a2[i] = *(const unsigned long long*)(sA + (ty * 8 + i) * SAS + 2 * kp);
#pragma unroll
            for (int j = 0; j < 4; ++j)
                b2[j] = *(const unsigned long long*)(sB + (tx * 4 + j) * SBS + 2 * kp);
#pragma unroll
            for (int i = 0; i < 8; ++i)
#pragma unroll
                for (int j = 0; j < 4; ++j)
                    ffma2(acc2[i][j], a2[i], b2[j]);
        }
        __syncthreads();
    }

    const int col = c0 + tx * 4;
    float4 bi = *(const float4*)(bih + col);
    float4 bh = *(const float4*)(bhh + col);
    float4 bias;
    bias.x = bi.x + bh.x; bias.y = bi.y + bh.y;
    bias.z = bi.z + bh.z; bias.w = bi.w + bh.w;

#pragma unroll
    for (int i = 0; i < 8; ++i) {
        const int n = n0 + ty * 8 + i;
        const int b = n >> 10;
        const int t = n & 1023;
        float4 o;
        o.x = acc_sum(acc2[i][0]) + bias.x;
        o.y = acc_sum(acc2[i][1]) + bias.y;
        o.z = acc_sum(acc2[i][2]) + bias.z;
        o.w = acc_sum(acc2[i][3]) + bias.w;
        *(float4*)&g_Xg[((size_t)(t * BATCH + b)) * G4 + col] = o;
    }
}

// ======================= Kernel 2: persistent recurrence ===================
// 128 blocks x 512 threads. Block owns 8 hidden units = 32 gate rows.
// sWT transposed in SMEM: [kp][lr] float2. Warp w: e = w>>1 (K-eighth:
// kpl = 8*kk + e), rh = w&1 (row half). Lane: rg = lane>>3 -> rows
// rbase = rh*16 + rg*4; bp = lane&7 -> batches 4bp..4bp+3.
// Thread: 4 rows x 4 batches = 16 f32x2 accumulators.
// h staged via cp.async.bulk (1 DMA instr per 16KB chunk, mbarrier completion)
// instead of 8192 per-thread LDGSTS — frees the L1tex/LSU pipe for the
// compute LDS traffic. Double-buffered; post-compute __syncthreads gates
// buffer reuse. Grid barrier: single atomicAdd counter.
__global__ __launch_bounds__(NTH, 1) void lstm_rec(const float* __restrict__ Whh,
                                                   float* __restrict__ out) {
    extern __shared__ float smem[];
    float* sWT = smem;                         // KP*64 floats = 128KB
    float* sH  = smem + KP * 64;               // 2 x CHBYTES = 32KB
    __shared__ float sGpart[8][32 * GSTR];     // 33.8KB static
    __shared__ unsigned long long sMbar[2];

    const int tid  = threadIdx.x;
    const int blk  = blockIdx.x;
    const int w    = tid >> 5;
    const int lane = tid & 31;
    const int e    = w >> 1;                   // K-eighth
    const int rh   = w & 1;                    // row half
    const int rg   = lane >> 3;
    const int bp   = lane & 7;
    const int rbase = rh * 16 + rg * 4;

    // epilogue mapping (tid < 256): one cell per thread
    const int uu = tid & 7;
    const int bb = (tid >> 3) & 31;
    const int gu = blk * 8 + uu;

    const unsigned sHaddr = (unsigned)__cvta_generic_to_shared(sH);
    const unsigned mb0 = (unsigned)__cvta_generic_to_shared(&sMbar[0]);
    const unsigned mb1 = (unsigned)__cvta_generic_to_shared(&sMbar[1]);

    // ---- init: W transpose into SMEM, mbarriers, zero h[0] ----
    for (int i = tid; i < 32 * (HDIM / 4); i += NTH) {
        const int lr = i >> 8;                  // 256 float4 per row
        const int q  = i & 255;                 // k = 4q..4q+3 -> kp 2q, 2q+1
        const int g = lr >> 3, u = lr & 7;
        const int grow = g * HDIM + blk * 8 + u;
        float4 v = *(const float4*)(Whh + (size_t)grow * HDIM + 4 * q);
        sWT[(2 * q) * 64 + lr * 2]     = v.x;
        sWT[(2 * q) * 64 + lr * 2 + 1] = v.y;
        sWT[(2 * q + 1) * 64 + lr * 2]     = v.z;
        sWT[(2 * q + 1) * 64 + lr * 2 + 1] = v.w;
    }
    if (tid == 0) { mbar_init(mb0, 1); mbar_init(mb1, 1); }
    if (tid < 256) g_h[0][(gu >> 1) * 64 + bb * 2 + (gu & 1)] = 0.f;
    float cs = 0.f;
    unsigned ph0 = 0, ph1 = 0;
    __threadfence();
    asm volatile("fence.proxy.async.shared::cta;" ::: "memory");
    __syncthreads();

    for (int t = 0; t < TLEN; ++t) {
        // ---- prefetch Xg for this thread's cell (pre-barrier OK) ----
        float x_i = 0.f, x_f = 0.f, x_g = 0.f, x_o = 0.f;
        if (tid < 256) {
            const size_t xb = ((size_t)(t * BATCH + bb)) * G4 + blk * 8 + uu;
            x_i = g_Xg[xb];
            x_f = g_Xg[xb + HDIM];
            x_g = g_Xg[xb + 2 * HDIM];
            x_o = g_Xg[xb + 3 * HDIM];
        }

        // ---- grid barrier (release: h stores ordered by this sync+fence) ----
        __syncthreads();
        if (tid == 0) {
            __threadfence();
            atomicAdd((unsigned*)&g_bar, 1u);
            const unsigned target = (unsigned)(t + 1) * GRID;
            while (g_bar < target) { }
            __threadfence();
        }
        __syncthreads();

        const float* hsrc = g_h[t & 1];
        // issue chunks 0 and 1 as bulk DMA
        if (tid == 0) {
            mbar_expect_tx(mb0, CHBYTES);
            bulk_g2s(sHaddr, hsrc, CHBYTES, mb0);
            mbar_expect_tx(mb1, CHBYTES);
            bulk_g2s(sHaddr + CHBYTES, hsrc + KPCH * 64, CHBYTES, mb1);
        }

        unsigned long long A[4][4];
#pragma unroll
        for (int i = 0; i < 4; ++i)
#pragma unroll
            for (int j = 0; j < 4; ++j) A[i][j] = 0ull;

#pragma unroll
        for (int c = 0; c < NCH; ++c) {
            // wait chunk c arrival (per-thread acquire)
            if (c & 1) { mbar_wait(mb1, ph1); ph1 ^= 1; }
            else       { mbar_wait(mb0, ph0); ph0 ^= 1; }

            const float* buf = sH + (c & 1) * (KPCH * 64);
            const float* wb  = sWT + (size_t)(c * KPCH) * 64;
#pragma unroll
            for (int kk = 0; kk < KPCH / 8; ++kk) {
                const int kpl = 8 * kk + e;
                const float* hb = buf + kpl * 64 + bp * 8;
                ulonglong2 hv0 = *(const ulonglong2*)(hb);      // batches 4bp, 4bp+1
                ulonglong2 hv1 = *(const ulonglong2*)(hb + 4);  // batches 4bp+2, 4bp+3
                const float* wp = wb + kpl * 64 + rbase * 2;
                ulonglong2 w01 = *(const ulonglong2*)(wp);      // rows rbase, +1
                ulonglong2 w23 = *(const ulonglong2*)(wp + 4);  // rows rbase+2, +3
                ffma2(A[0][0], w01.x, hv0.x); ffma2(A[0][1], w01.x, hv0.y);
                ffma2(A[0][2], w01.x, hv1.x); ffma2(A[0][3], w01.x, hv1.y);
                ffma2(A[1][0], w01.y, hv0.x); ffma2(A[1][1], w01.y, hv0.y);
                ffma2(A[1][2], w01.y, hv1.x); ffma2(A[1][3], w01.y, hv1.y);
                ffma2(A[2][0], w23.x, hv0.x); ffma2(A[2][1], w23.x, hv0.y);
                ffma2(A[2][2], w23.x, hv1.x); ffma2(A[2][3], w23.x, hv1.y);
                ffma2(A[3][0], w23.y, hv0.x); ffma2(A[3][1], w23.y, hv0.y);
                ffma2(A[3][2], w23.y, hv1.x); ffma2(A[3][3], w23.y, hv1.y);
            }
            __syncthreads();   // all consumers done with buf (gates DMA reuse)
            if (c + 2 < NCH && tid == 0) {
                const unsigned dst = sHaddr + (unsigned)((c & 1) * CHBYTES);
                const unsigned mb = (c & 1) ? mb1 : mb0;
                mbar_expect_tx(mb, CHBYTES);
                bulk_g2s(dst, hsrc + (c + 2) * (KPCH * 64), CHBYTES, mb);
            }
        }

        // ---- publish partial gate pre-activations [e][lr][b] ----
        {
            float* gp = sGpart[e];
#pragma unroll
            for (int ri = 0; ri < 4; ++ri)
#pragma unroll
                for (int bj = 0; bj < 4; ++bj)
                    gp[(rbase + ri) * GSTR + 4 * bp + bj] = acc_sum(A[ri][bj]);
        }
        __syncthreads();

        // ---- cell update: threads 0..255, one (uu, bb) each ----
        if (tid < 256) {
            const int ri  = (0 * 8 + uu) * GSTR + bb;
            const int rf  = (1 * 8 + uu) * GSTR + bb;
            const int rgi = (2 * 8 + uu) * GSTR + bb;
            const int ro  = (3 * 8 + uu) * GSTR + bb;
            float pi = x_i, pf = x_f, pg = x_g, po = x_o;
#pragma unroll
            for (int p = 0; p < 8; ++p) {
                pi += sGpart[p][ri];
                pf += sGpart[p][rf];
                pg += sGpart[p][rgi];
                po += sGpart[p][ro];
            }

            const float cn = fmaf(sigm(pf), cs, sigm(pi) * tanh_f(pg));
            cs = cn;
            const float hn = sigm(po) * tanh_f(cn);

            g_h[(t + 1) & 1][(gu >> 1) * 64 + bb * 2 + (gu & 1)] = hn;
            out[(size_t)bb * TLEN * HDIM + (size_t)t * HDIM + gu] = hn;
            if (t == TLEN - 1) {
                const size_t OFF = (size_t)BATCH * TLEN * HDIM;
                out[OFF + (size_t)bb * HDIM + gu] = hn;                  // h_T
                out[OFF + BATCH * HDIM + (size_t)bb * HDIM + gu] = cn;   // c_T
            }
        }
        // next iteration's __syncthreads + tid0 fence release the h stores.
    }

    // ---- reset barrier state for graph replays ----
    __syncthreads();
    if (tid == 0) {
        const unsigned d = atomicAdd(&g_done, 1u);
        if (d == GRID - 1) {
            g_bar = 0;
            g_done = 0;
            __threadfence();
        }
    }
}

// =========================== launch ========================================
extern "C" void kernel_launch(void* const* d_in, const int* in_sizes, int n_in,
                              void* d_out, int out_size) {
    const float* X   = (const float*)d_in[0];
    const float* Wih = (const float*)d_in[1];
    const float* Whh = (const float*)d_in[2];
    const float* bih = (const float*)d_in[3];
    const float* bhh = (const float*)d_in[4];
    float* out = (float*)d_out;

    const int dyn_smem = (KP * 64) * (int)sizeof(float) + 2 * CHBYTES; // 163840 B
    cudaFuncSetAttribute(lstm_rec, cudaFuncAttributeMaxDynamicSharedMemorySize, dyn_smem);

    xg_gemm<<<dim3(G4 / BN, (BATCH * TLEN) / BM), 256>>>(X, Wih, bih, bhh);
    lstm_rec<<<GRID, NTH, dyn_smem>>>(Whh, out);
}

// round 16
// speedup vs baseline: 1.2276x; 1.2276x over previous
#include <cuda_runtime.h>
#include <cstdint>
#include <math.h>

#define BATCH 32
#define TLEN  1024
#define IDIM  512
#define HDIM  1024
#define G4    4096
#define KP    512          // k-pairs in recurrence (HDIM/2)
#define KPCH  128          // k-pairs per staged chunk
#define NCH   4
#define CHBYTES (KPCH * 64 * 4)   // 32768 bytes per chunk
#define GRID  128
#define NTH   256
#define GSTR  33

// ---------------- static device scratch (allocation-free) ------------------
__device__ float g_Xg[(size_t)BATCH * TLEN * G4];   // [t*32+b][4096], includes biases
__device__ float g_h[2][HDIM * BATCH];              // [kp][b] float2: idx kp*64 + b*2 + par
__device__ volatile unsigned g_bar;
__device__ unsigned g_done;

// ---------------- helpers ---------------------------------------------------
__device__ __forceinline__ void ffma2(unsigned long long& d,
                                      unsigned long long a,
                                      unsigned long long b) {
    asm("fma.rn.f32x2 %0, %1, %2, %0;" : "+l"(d) : "l"(a), "l"(b));
}
__device__ __forceinline__ float acc_sum(unsigned long long v) {
    return __uint_as_float((unsigned)v) + __uint_as_float((unsigned)(v >> 32));
}
__device__ __forceinline__ float sigm(float x) { return 1.f / (1.f + __expf(-x)); }
__device__ __forceinline__ float tanh_f(float x) { return 1.f - 2.f / (__expf(2.f * x) + 1.f); }

__device__ __forceinline__ void mbar_init(unsigned mbar, unsigned cnt) {
    asm volatile("mbarrier.init.shared.b64 [%0], %1;" :: "r"(mbar), "r"(cnt) : "memory");
}
__device__ __forceinline__ void mbar_expect_tx(unsigned mbar, unsigned bytes) {
    asm volatile("mbarrier.arrive.expect_tx.shared.b64 _, [%0], %1;"
                 :: "r"(mbar), "r"(bytes) : "memory");
}
__device__ __forceinline__ void bulk_g2s(unsigned sdst, const void* gsrc,
                                         unsigned bytes, unsigned mbar) {
    asm volatile(
        "cp.async.bulk.shared::cta.global.mbarrier::complete_tx::bytes [%0], [%1], %2, [%3];"
        :: "r"(sdst), "l"(gsrc), "r"(bytes), "r"(mbar) : "memory");
}
__device__ __forceinline__ void mbar_wait(unsigned mbar, unsigned parity) {
    unsigned done;
    asm volatile(
        "{\n\t.reg .pred p;\n\t"
        "mbarrier.try_wait.parity.acquire.cta.shared::cta.b64 p, [%1], %2;\n\t"
        "selp.b32 %0, 1, 0, p;\n\t}"
        : "=r"(done) : "r"(mbar), "r"(parity) : "memory");
    if (!done) {
        asm volatile(
            "{\n\t.reg .pred P1;\n\t"
            "WL_%=:\n\t"
            "mbarrier.try_wait.parity.acquire.cta.shared::cta.b64 P1, [%0], %1, 0x989680;\n\t"
            "@P1 bra.uni WD_%=;\n\t"
            "bra.uni WL_%=;\n\t"
            "WD_%=:\n\t}"
            :: "r"(mbar), "r"(parity) : "memory");
    }
}

// ======================= Kernel 1: Xg = X @ W_ih^T + (b_ih + b_hh) =========
#define BM 128
#define BN 64
#define BK 16
#define SAS 18
#define SBS 18

__global__ __launch_bounds__(256) void xg_gemm(const float* __restrict__ X,
                                               const float* __restrict__ Wih,
                                               const float* __restrict__ bih,
                                               const float* __restrict__ bhh) {
    __shared__ float sA[BM * SAS];
    __shared__ float sB[BN * SBS];

    const int tid = threadIdx.x;
    const int tx = tid & 15;
    const int ty = tid >> 4;
    const int n0 = blockIdx.y * BM;
    const int c0 = blockIdx.x * BN;

    unsigned long long acc2[8][4];
#pragma unroll
    for (int i = 0; i < 8; ++i)
#pragma unroll
        for (int j = 0; j < 4; ++j) acc2[i][j] = 0ull;

    for (int k0 = 0; k0 < IDIM; k0 += BK) {
        {
            const int m = tid >> 1;
            const int kk = (tid & 1) * 8;
            const float* src = X + (size_t)(n0 + m) * IDIM + k0 + kk;
            float4 v0 = *(const float4*)(src);
            float4 v1 = *(const float4*)(src + 4);
            float* d = sA + m * SAS + kk;
            d[0] = v0.x; d[1] = v0.y; d[2] = v0.z; d[3] = v0.w;
            d[4] = v1.x; d[5] = v1.y; d[6] = v1.z; d[7] = v1.w;
        }
        {
            const int m = tid >> 2;
            const int kk = (tid & 3) * 4;
            float4 v = *(const float4*)(Wih + (size_t)(c0 + m) * IDIM + k0 + kk);
            float* d = sB + m * SBS + kk;
            d[0] = v.x; d[1] = v.y; d[2] = v.z; d[3] = v.w;
        }
        __syncthreads();

#pragma unroll
        for (int kp = 0; kp < BK / 2; ++kp) {
            unsigned long long a2[8], b2[4];
#pragma unroll
            for (int i = 0; i < 8; ++i)
                a2[i] = *(const unsigned long long*)(sA + (ty * 8 + i) * SAS + 2 * kp);
#pragma unroll
            for (int j = 0; j < 4; ++j)
                b2[j] = *(const unsigned long long*)(sB + (tx * 4 + j) * SBS + 2 * kp);
#pragma unroll
            for (int i = 0; i < 8; ++i)
#pragma unroll
                for (int j = 0; j < 4; ++j)
                    ffma2(acc2[i][j], a2[i], b2[j]);
        }
        __syncthreads();
    }

    const int col = c0 + tx * 4;
    float4 bi = *(const float4*)(bih + col);
    float4 bh = *(const float4*)(bhh + col);
    float4 bias;
    bias.x = bi.x + bh.x; bias.y = bi.y + bh.y;
    bias.z = bi.z + bh.z; bias.w = bi.w + bh.w;

#pragma unroll
    for (int i = 0; i < 8; ++i) {
        const int n = n0 + ty * 8 + i;
        const int b = n >> 10;
        const int t = n & 1023;
        float4 o;
        o.x = acc_sum(acc2[i][0]) + bias.x;
        o.y = acc_sum(acc2[i][1]) + bias.y;
        o.z = acc_sum(acc2[i][2]) + bias.z;
        o.w = acc_sum(acc2[i][3]) + bias.w;
        *(float4*)&g_Xg[((size_t)(t * BATCH + b)) * G4 + col] = o;
    }
}

// ======================= Kernel 2: persistent recurrence ===================
// 128 blocks x 256 threads (8 warps). Block owns 8 hidden units = 32 gate rows.
// sWT transposed in SMEM: [kp][lr] float2. Warp w = K-eighth e: kpl = 8*kk + e.
// Lane: rq = lane>>3 -> rows rq*8..rq*8+7 (T=8); bp = lane&7 -> batches
// 4bp..4bp+3 (U=4). Thread: 8x4 = 32 f32x2 accumulators.
// Crossbar phases/step: 8 warps x 64 kpl x 2(8+4) = 12.3K (vs 16.4K in R14).
// h staged via cp.async.bulk, 32KB chunks, double-buffered (NCH=4 -> only 4
// sync points/step). Grid barrier: single atomicAdd counter.
__global__ __launch_bounds__(NTH, 1) void lstm_rec(const float* __restrict__ Whh,
                                                   float* __restrict__ out) {
    extern __shared__ float smem[];
    float* sWT = smem;                         // KP*64 floats = 128KB
    float* sH  = smem + KP * 64;               // 2 x CHBYTES = 64KB
    __shared__ float sGpart[8][32 * GSTR];     // 33.8KB static
    __shared__ unsigned long long sMbar[2];

    const int tid  = threadIdx.x;
    const int blk  = blockIdx.x;
    const int e    = tid >> 5;                 // warp = K-eighth
    const int lane = tid & 31;
    const int rq   = lane >> 3;                // row quad: rows rq*8..rq*8+7
    const int bp   = lane & 7;                 // batches 4bp..4bp+3

    // epilogue mapping: one cell per thread
    const int uu = tid & 7;
    const int bb = tid >> 3;
    const int gu = blk * 8 + uu;

    const unsigned sHaddr = (unsigned)__cvta_generic_to_shared(sH);
    const unsigned mb0 = (unsigned)__cvta_generic_to_shared(&sMbar[0]);
    const unsigned mb1 = (unsigned)__cvta_generic_to_shared(&sMbar[1]);

    // ---- init: W transpose into SMEM, mbarriers, zero h[0] ----
    for (int i = tid; i < 32 * (HDIM / 4); i += NTH) {
        const int lr = i >> 8;                  // 256 float4 per row
        const int q  = i & 255;                 // k = 4q..4q+3 -> kp 2q, 2q+1
        const int g = lr >> 3, u = lr & 7;
        const int grow = g * HDIM + blk * 8 + u;
        float4 v = *(const float4*)(Whh + (size_t)grow * HDIM + 4 * q);
        sWT[(2 * q) * 64 + lr * 2]     = v.x;
        sWT[(2 * q) * 64 + lr * 2 + 1] = v.y;
        sWT[(2 * q + 1) * 64 + lr * 2]     = v.z;
        sWT[(2 * q + 1) * 64 + lr * 2 + 1] = v.w;
    }
    if (tid == 0) { mbar_init(mb0, 1); mbar_init(mb1, 1); }
    g_h[0][(gu >> 1) * 64 + bb * 2 + (gu & 1)] = 0.f;
    float cs = 0.f;
    unsigned ph0 = 0, ph1 = 0;
    __threadfence();
    asm volatile("fence.proxy.async.shared::cta;" ::: "memory");
    __syncthreads();

    for (int t = 0; t < TLEN; ++t) {
        // ---- prefetch Xg for this thread's cell (pre-barrier OK) ----
        const size_t xb = ((size_t)(t * BATCH + bb)) * G4 + blk * 8 + uu;
        const float x_i = g_Xg[xb];
        const float x_f = g_Xg[xb + HDIM];
        const float x_g = g_Xg[xb + 2 * HDIM];
        const float x_o = g_Xg[xb + 3 * HDIM];

        // ---- grid barrier (release: h stores ordered by this sync+fence) ----
        __syncthreads();
        if (tid == 0) {
            __threadfence();
            atomicAdd((unsigned*)&g_bar, 1u);
            const unsigned target = (unsigned)(t + 1) * GRID;
            while (g_bar < target) { }
            __threadfence();
        }
        __syncthreads();

        const float* hsrc = g_h[t & 1];
        if (tid == 0) {
            mbar_expect_tx(mb0, CHBYTES);
            bulk_g2s(sHaddr, hsrc, CHBYTES, mb0);
            mbar_expect_tx(mb1, CHBYTES);
            bulk_g2s(sHaddr + CHBYTES, hsrc + KPCH * 64, CHBYTES, mb1);
        }

        unsigned long long A[8][4];
#pragma unroll
        for (int i = 0; i < 8; ++i)
#pragma unroll
            for (int j = 0; j < 4; ++j) A[i][j] = 0ull;

#pragma unroll
        for (int c = 0; c < NCH; ++c) {
            if (c & 1) { mbar_wait(mb1, ph1); ph1 ^= 1; }
            else       { mbar_wait(mb0, ph0); ph0 ^= 1; }

            const float* buf = sH + (c & 1) * (KPCH * 64);
            const float* wb  = sWT + (size_t)(c * KPCH) * 64;
#pragma unroll 8
            for (int kk = 0; kk < KPCH / 8; ++kk) {
                const int kic = 8 * kk + e;                   // kpl within chunk
                const float* hb = buf + kic * 64 + bp * 8;    // 4 f32x2, contiguous
                ulonglong2 hv0 = *(const ulonglong2*)(hb);
                ulonglong2 hv1 = *(const ulonglong2*)(hb + 4);
                const float* wp = wb + kic * 64 + rq * 16;    // 8 rows' f32x2
                ulonglong2 w01 = *(const ulonglong2*)(wp);
                ulonglong2 w23 = *(const ulonglong2*)(wp + 4);
                ulonglong2 w45 = *(const ulonglong2*)(wp + 8);
                ulonglong2 w67 = *(const ulonglong2*)(wp + 12);
                ffma2(A[0][0], w01.x, hv0.x); ffma2(A[0][1], w01.x, hv0.y);
                ffma2(A[0][2], w01.x, hv1.x); ffma2(A[0][3], w01.x, hv1.y);
                ffma2(A[1][0], w01.y, hv0.x); ffma2(A[1][1], w01.y, hv0.y);
                ffma2(A[1][2], w01.y, hv1.x); ffma2(A[1][3], w01.y, hv1.y);
                ffma2(A[2][0], w23.x, hv0.x); ffma2(A[2][1], w23.x, hv0.y);
                ffma2(A[2][2], w23.x, hv1.x); ffma2(A[2][3], w23.x, hv1.y);
                ffma2(A[3][0], w23.y, hv0.x); ffma2(A[3][1], w23.y, hv0.y);
                ffma2(A[3][2], w23.y, hv1.x); ffma2(A[3][3], w23.y, hv1.y);
                ffma2(A[4][0], w45.x, hv0.x); ffma2(A[4][1], w45.x, hv0.y);
                ffma2(A[4][2], w45.x, hv1.x); ffma2(A[4][3], w45.x, hv1.y);
                ffma2(A[5][0], w45.y, hv0.x); ffma2(A[5][1], w45.y, hv0.y);
                ffma2(A[5][2], w45.y, hv1.x); ffma2(A[5][3], w45.y, hv1.y);
                ffma2(A[6][0], w67.x, hv0.x); ffma2(A[6][1], w67.x, hv0.y);
                ffma2(A[6][2], w67.x, hv1.x); ffma2(A[6][3], w67.x, hv1.y);
                ffma2(A[7][0], w67.y, hv0.x); ffma2(A[7][1], w67.y, hv0.y);
                ffma2(A[7][2], w67.y, hv1.x); ffma2(A[7][3], w67.y, hv1.y);
            }
            __syncthreads();   // all consumers done with buf (gates DMA reuse)
            if (c + 2 < NCH && tid == 0) {
                const unsigned dst = sHaddr + (unsigned)((c & 1) * CHBYTES);
                const unsigned mb = (c & 1) ? mb1 : mb0;
                mbar_expect_tx(mb, CHBYTES);
                bulk_g2s(dst, hsrc + (c + 2) * (KPCH * 64), CHBYTES, mb);
            }
        }

        // ---- publish partial gate pre-activations [e][lr][b] ----
        {
            float* gp = sGpart[e];
#pragma unroll
            for (int ri = 0; ri < 8; ++ri)
#pragma unroll
                for (int bj = 0; bj < 4; ++bj)
                    gp[(rq * 8 + ri) * GSTR + 4 * bp + bj] = acc_sum(A[ri][bj]);
        }
        __syncthreads();

        // ---- cell update: one (uu, bb) per thread; bias already in x_* ----
        {
            const int ri  = (0 * 8 + uu) * GSTR + bb;
            const int rf  = (1 * 8 + uu) * GSTR + bb;
            const int rgi = (2 * 8 + uu) * GSTR + bb;
            const int ro  = (3 * 8 + uu) * GSTR + bb;
            float pi = x_i, pf = x_f, pg = x_g, po = x_o;
#pragma unroll
            for (int p = 0; p < 8; ++p) {
                pi += sGpart[p][ri];
                pf += sGpart[p][rf];
                pg += sGpart[p][rgi];
                po += sGpart[p][ro];
            }

            const float cn = fmaf(sigm(pf), cs, sigm(pi) * tanh_f(pg));
            cs = cn;
            const float hn = sigm(po) * tanh_f(cn);

            g_h[(t + 1) & 1][(gu >> 1) * 64 + bb * 2 + (gu & 1)] = hn;
            out[(size_t)bb * TLEN * HDIM + (size_t)t * HDIM + gu] = hn;
            if (t == TLEN - 1) {
                const size_t OFF = (size_t)BATCH * TLEN * HDIM;
                out[OFF + (size_t)bb * HDIM + gu] = hn;                  // h_T
                out[OFF + BATCH * HDIM + (size_t)bb * HDIM + gu] = cn;   // c_T
            }
        }
        // next iteration's __syncthreads + tid0 fence release the h stores.
    }

    // ---- reset barrier state for graph replays ----
    __syncthreads();
    if (tid == 0) {
        const unsigned d = atomicAdd(&g_done, 1u);
        if (d == GRID - 1) {
            g_bar = 0;
            g_done = 0;
            __threadfence();
        }
    }
}

// =========================== launch ========================================
extern "C" void kernel_launch(void* const* d_in, const int* in_sizes, int n_in,
                              void* d_out, int out_size) {
    const float* X   = (const float*)d_in[0];
    const float* Wih = (const float*)d_in[1];
    const float* Whh = (const float*)d_in[2];
    const float* bih = (const float*)d_in[3];
    const float* bhh = (const float*)d_in[4];
    float* out = (float*)d_out;

    const int dyn_smem = (KP * 64) * (int)sizeof(float) + 2 * CHBYTES; // 196608 B
    cudaFuncSetAttribute(lstm_rec, cudaFuncAttributeMaxDynamicSharedMemorySize, dyn_smem);

    xg_gemm<<<dim3(G4 / BN, (BATCH * TLEN) / BM), 256>>>(X, Wih, bih, bhh);
    lstm_rec<<<GRID, NTH, dyn_smem>>>(Whh, out);
}